// round 16
// baseline (speedup 1.0000x reference)
#include <cuda_runtime.h>
#include <cuda_fp16.h>
#include <math.h>
#include <stdint.h>

#define EDIM 1024
#define HNUM 16
#define DDIM 64
#define MAXL 512
#define BATCH 4
#define SEQ 1024
#define ROWS (BATCH * SEQ)   // 4096
#define EPSV 1e-5f

// ---------------- scratch ----------------
__device__ float g_x1[ROWS * EDIM];
__device__ __align__(16) __half g_xn  [ROWS * EDIM];
__device__ __align__(16) __half g_qkvh[ROWS * 3 * EDIM];
__device__ __align__(16) __half g_att [ROWS * EDIM];
__device__ __align__(16) __half g_xm  [ROWS * EDIM];
__device__ __align__(16) __half g_hb  [ROWS * 4 * EDIM];
__device__ __align__(16) __half g_ipw16[3 * EDIM * EDIM];
__device__ __align__(16) __half g_ow16 [EDIM * EDIM];
__device__ __align__(16) __half g_w116 [4 * EDIM * EDIM];
__device__ __align__(16) __half g_w216 [4 * EDIM * EDIM];

// ======================= helpers =======================
__device__ __forceinline__ uint32_t smem_u32(const void* p) {
    uint32_t a;
    asm("{ .reg .u64 t; cvta.to.shared.u64 t, %1; cvt.u32.u64 %0, t; }" : "=r"(a) : "l"(p));
    return a;
}
__device__ __forceinline__ void cpa16(uint32_t dst, const void* src) {
    asm volatile("cp.async.cg.shared.global [%0], [%1], 16;" :: "r"(dst), "l"(src));
}
__device__ __forceinline__ void ldm4(uint32_t* r, uint32_t addr) {
    asm volatile("ldmatrix.sync.aligned.m8n8.x4.shared.b16 {%0,%1,%2,%3}, [%4];"
                 : "=r"(r[0]), "=r"(r[1]), "=r"(r[2]), "=r"(r[3]) : "r"(addr));
}
__device__ __forceinline__ void ldm4t(uint32_t* r, uint32_t addr) {
    asm volatile("ldmatrix.sync.aligned.m8n8.x4.trans.shared.b16 {%0,%1,%2,%3}, [%4];"
                 : "=r"(r[0]), "=r"(r[1]), "=r"(r[2]), "=r"(r[3]) : "r"(addr));
}
__device__ __forceinline__ void mma16816(float* c, const uint32_t* a, const uint32_t* b) {
    asm volatile(
        "mma.sync.aligned.m16n8k16.row.col.f32.f16.f16.f32 "
        "{%0,%1,%2,%3}, {%4,%5,%6,%7}, {%8,%9}, {%0,%1,%2,%3};"
        : "+f"(c[0]), "+f"(c[1]), "+f"(c[2]), "+f"(c[3])
        : "r"(a[0]), "r"(a[1]), "r"(a[2]), "r"(a[3]), "r"(b[0]), "r"(b[1]));
}
__device__ __forceinline__ uint32_t packh2(float a, float b) {
    __half2 h = __floats2half2_rn(a, b);
    return *(uint32_t*)&h;
}
__device__ __forceinline__ uint32_t swz(int r, int c16) {
    return (uint32_t)(r * 128 + ((c16 ^ (r & 7)) << 4));
}

// ======================= fused weight convert fp32->fp16 =======================
#define N4_IPW (3 * EDIM * EDIM / 4)
#define N4_OW  (EDIM * EDIM / 4)
#define N4_W1  (4 * EDIM * EDIM / 4)
#define N4_W2  (4 * EDIM * EDIM / 4)
#define N4_TOT (N4_IPW + N4_OW + N4_W1 + N4_W2)

__global__ void convert_all_kernel(const float4* __restrict__ ipw,
                                   const float4* __restrict__ ow,
                                   const float4* __restrict__ w1,
                                   const float4* __restrict__ w2,
                                   __half2* __restrict__ ipwo, __half2* __restrict__ owo,
                                   __half2* __restrict__ w1o,  __half2* __restrict__ w2o) {
    int i = blockIdx.x * 256 + threadIdx.x;
    if (i >= N4_TOT) return;
    const float4* src;
    __half2* dst;
    int j = i;
    if (j < N4_IPW) { src = ipw; dst = ipwo; }
    else if ((j -= N4_IPW) < N4_OW) { src = ow; dst = owo; }
    else if ((j -= N4_OW) < N4_W1)  { src = w1; dst = w1o; }
    else { j -= N4_W1; src = w2; dst = w2o; }
    float4 f = src[j];
    dst[2 * j]     = __floats2half2_rn(f.x, f.y);
    dst[2 * j + 1] = __floats2half2_rn(f.z, f.w);
}

// ======================= LayerNorm (fp32 -> fp16) =======================
__global__ void ln_kernel(const float* __restrict__ x,
                          const float* __restrict__ g,
                          const float* __restrict__ b,
                          __half* __restrict__ o) {
    int row = blockIdx.x;
    int tid = threadIdx.x;
    const float4* xr = (const float4*)(x + (size_t)row * EDIM);
    float4 v = xr[tid];
    float s  = v.x + v.y + v.z + v.w;
    float ss = v.x * v.x + v.y * v.y + v.z * v.z + v.w * v.w;
#pragma unroll
    for (int of = 16; of > 0; of >>= 1) {
        s  += __shfl_xor_sync(0xffffffffu, s,  of);
        ss += __shfl_xor_sync(0xffffffffu, ss, of);
    }
    __shared__ float rs[8], rss[8];
    __shared__ float s_mu, s_rstd;
    if ((tid & 31) == 0) { rs[tid >> 5] = s; rss[tid >> 5] = ss; }
    __syncthreads();
    if (tid == 0) {
        float S = 0.f, SS = 0.f;
#pragma unroll
        for (int i = 0; i < 8; i++) { S += rs[i]; SS += rss[i]; }
        float mu = S * (1.0f / EDIM);
        float var = SS * (1.0f / EDIM) - mu * mu;
        s_mu = mu; s_rstd = rsqrtf(var + EPSV);
    }
    __syncthreads();
    float mu = s_mu, rstd = s_rstd;
    float4 gg = ((const float4*)g)[tid];
    float4 bb = ((const float4*)b)[tid];
    __half2* po = (__half2*)(o + (size_t)row * EDIM);
    po[2 * tid]     = __floats2half2_rn((v.x - mu) * rstd * gg.x + bb.x,
                                        (v.y - mu) * rstd * gg.y + bb.y);
    po[2 * tid + 1] = __floats2half2_rn((v.z - mu) * rstd * gg.z + bb.z,
                                        (v.w - mu) * rstd * gg.w + bb.w);
}

// ======================= fp16 GEMM: BM=256 BN=128 BK=64 ====================
// 512 thr = 16 warps (4m x 4n), warp tile 64x32, 3-stage cp.async, 1 CTA/SM.
// Taller M-tile halves B-operand L2 traffic (L2-bound regime).
#define TILA 32768u                 // 256 rows * 128B
#define TILB 16384u                 // 128 rows * 128B
#define STG2 (TILA + TILB)          // 48KB / stage
#define GSMEM (3u * STG2)           // 147456

template <bool RELU, bool RES, bool OUTF32>
__global__ void __launch_bounds__(512, 1)
gemm_mma(const __half* __restrict__ A, const __half* __restrict__ B,
         const float* __restrict__ bias, const float* __restrict__ res,
         float* __restrict__ C, __half* __restrict__ Ch, int Nc, int K) {
    extern __shared__ char sm[];
    uint32_t sb = smem_u32(sm);
    int tid = threadIdx.x;
    int wid = tid >> 5, lane = tid & 31;
    int wm = wid & 3, wn = wid >> 2;          // 4 m-warps x 4 n-warps
    int brow = blockIdx.y * 256, bcol = blockIdx.x * 128;

    float acc[4][4][4];
#pragma unroll
    for (int i = 0; i < 4; i++)
#pragma unroll
        for (int j = 0; j < 4; j++)
#pragma unroll
            for (int k = 0; k < 4; k++) acc[i][j][k] = 0.f;

    int nchunk = K >> 6;
    auto load_stage = [&](int st, int k0) {
        uint32_t base = sb + (uint32_t)st * STG2;
#pragma unroll
        for (int i = 0; i < 6; i++) {
            int idx = tid + i * 512;           // 0..3071 16B-chunks
            int c16 = idx & 7;
            uint32_t d;
            const __half* src;
            if (idx < 2048) {                  // A: 256 rows
                int r = idx >> 3;
                d = base + swz(r, c16);
                src = A + (size_t)(brow + r) * K + k0 + c16 * 8;
            } else {                           // B: 128 rows
                int r = (idx - 2048) >> 3;
                d = base + TILA + swz(r, c16);
                src = B + (size_t)(bcol + r) * K + k0 + c16 * 8;
            }
            cpa16(d, src);
        }
    };

    load_stage(0, 0);
    asm volatile("cp.async.commit_group;" ::: "memory");
    if (nchunk > 1) load_stage(1, 64);
    asm volatile("cp.async.commit_group;" ::: "memory");

    int l15 = lane & 15;
    int ac16 = (lane & 16) ? 1 : 0;
    int brr = (lane & 7) + ((lane & 16) ? 8 : 0);
    int bc16 = (lane & 8) ? 1 : 0;

    int stage = 0;
    for (int ch = 0; ch < nchunk; ch++) {
        asm volatile("cp.async.wait_group 1;" ::: "memory");
        __syncthreads();
        if (ch + 2 < nchunk) {
            int ns = stage + 2; if (ns >= 3) ns -= 3;
            load_stage(ns, (ch + 2) * 64);
        }
        asm volatile("cp.async.commit_group;" ::: "memory");

        uint32_t base = sb + (uint32_t)stage * STG2;
#pragma unroll
        for (int kc = 0; kc < 4; kc++) {
            uint32_t kb[2][4];
#pragma unroll
            for (int p = 0; p < 2; p++)
                ldm4(kb[p], base + TILA + swz(wn * 32 + p * 16 + brr, kc * 2 + bc16));
#pragma unroll
            for (int mf = 0; mf < 4; mf++) {
                uint32_t a[4];
                ldm4(a, base + swz(wm * 64 + mf * 16 + l15, kc * 2 + ac16));
#pragma unroll
                for (int nf = 0; nf < 4; nf++)
                    mma16816(acc[mf][nf], a, &kb[nf >> 1][(nf & 1) * 2]);
            }
        }
        if (++stage >= 3) stage = 0;
    }
    __syncthreads();

    int gid = lane >> 2, tig = lane & 3;
#pragma unroll
    for (int mf = 0; mf < 4; mf++) {
#pragma unroll
        for (int nf = 0; nf < 4; nf++) {
            int col = bcol + wn * 32 + nf * 8 + tig * 2;
            float b0 = bias[col], b1 = bias[col + 1];
#pragma unroll
            for (int hr = 0; hr < 2; hr++) {
                int row = brow + wm * 64 + mf * 16 + gid + hr * 8;
                float v0 = acc[mf][nf][hr * 2 + 0] + b0;
                float v1 = acc[mf][nf][hr * 2 + 1] + b1;
                if (RELU) { v0 = fmaxf(v0, 0.f); v1 = fmaxf(v1, 0.f); }
                if (RES) {
                    float2 r2 = *(const float2*)(res + (size_t)row * Nc + col);
                    v0 += r2.x; v1 += r2.y;
                }
                if (OUTF32) {
                    float2 o2; o2.x = v0; o2.y = v1;
                    *(float2*)(C + (size_t)row * Nc + col) = o2;
                } else {
                    *(__half2*)(Ch + (size_t)row * Nc + col) = __floats2half2_rn(v0, v1);
                }
            }
        }
    }
}

// ======================= flash attention (mma.sync fp16) =======================
#define AT_SQ   0u
#define AT_RP   16384u
#define AT_ST   18432u
#define AT_SMEM (18432u + 2u * 16384u)

__global__ void __launch_bounds__(256, 2)
attn_kernel(const __half* __restrict__ qkv, const float* __restrict__ relp,
            __half* __restrict__ outp) {
    extern __shared__ char sm[];
    uint32_t sb = smem_u32(sm);
    float* srelp = (float*)(sm + AT_RP);
    int tid = threadIdx.x;
    int w = tid >> 5, lane = tid & 31;
    int gid = lane >> 2, tig = lane & 3;
    int qt = gridDim.x - 1 - blockIdx.x;      // heavy tiles first
    int q0 = qt * 128;
    int bh = blockIdx.y;
    int b = bh >> 4, h = bh & 15;

#pragma unroll
    for (int i = 0; i < 2; i++) srelp[tid + i * 256] = relp[h * MAXL + tid + i * 256];
#pragma unroll
    for (int i = 0; i < 4; i++) {
        int idx = tid + i * 256;
        int r = idx >> 3, c16 = idx & 7;
        uint4 q4 = *(const uint4*)(qkv + (size_t)(b * SEQ + q0 + r) * 3 * EDIM +
                                   h * DDIM + c16 * 8);
        *(uint4*)(sm + AT_SQ + swz(r, c16)) = q4;
    }
    __syncthreads();

    uint32_t qf[4][4];
    int l15 = lane & 15;
    int ac16 = (lane & 16) ? 1 : 0;
#pragma unroll
    for (int kc = 0; kc < 4; kc++)
        ldm4(qf[kc], sb + AT_SQ + swz(w * 16 + l15, kc * 2 + ac16));

    float o[8][4];
#pragma unroll
    for (int nf = 0; nf < 8; nf++)
#pragma unroll
        for (int e = 0; e < 4; e++) o[nf][e] = 0.f;
    float m0 = -1e30f, m1 = -1e30f, l0 = 0.f, l1 = 0.f;

    int ktlo = 2 * qt - 8; if (ktlo < 0) ktlo = 0;
    int kthi = 2 * qt + 1;
    int nt = kthi - ktlo + 1;
    int qlo = q0 + w * 16, qhi = qlo + 15;

    auto load_kv = [&](int st, int kt) {
        uint32_t base = sb + AT_ST + (uint32_t)st * 16384u;
        int k0 = kt * 64;
#pragma unroll
        for (int i = 0; i < 4; i++) {
            int idx = tid + i * 256;
            int part = idx >> 9;
            int r = (idx & 511) >> 3, c16 = idx & 7;
            const __half* src = qkv + (size_t)(b * SEQ + k0 + r) * 3 * EDIM +
                                (part ? 2 * EDIM : EDIM) + h * DDIM + c16 * 8;
            cpa16(base + part * 8192u + swz(r, c16), src);
        }
    };

    load_kv(0, ktlo);
    asm volatile("cp.async.commit_group;" ::: "memory");

    int brr = (lane & 7) + ((lane & 16) ? 8 : 0);
    int bc16 = (lane & 8) ? 1 : 0;
    int vrr = (lane & 7) + ((lane & 8) ? 8 : 0);
    int vc16 = (lane & 16) ? 1 : 0;

    for (int it = 0; it < nt; it++) {
        int kt = ktlo + it, k0 = kt * 64;
        if (it + 1 < nt) load_kv((it + 1) & 1, kt + 1);
        asm volatile("cp.async.commit_group;" ::: "memory");
        asm volatile("cp.async.wait_group 1;" ::: "memory");
        __syncthreads();

        bool active = (k0 <= qhi) && (k0 + 63 >= qlo - (MAXL - 1));
        if (active) {
            uint32_t kbase = sb + AT_ST + (uint32_t)(it & 1) * 16384u;
            uint32_t vbase = kbase + 8192u;

            float s[8][4];
#pragma unroll
            for (int nf = 0; nf < 8; nf++)
#pragma unroll
                for (int e = 0; e < 4; e++) s[nf][e] = 0.f;
#pragma unroll
            for (int kc = 0; kc < 4; kc++) {
                uint32_t kb[4][4];
#pragma unroll
                for (int t = 0; t < 4; t++)
                    ldm4(kb[t], kbase + swz(t * 16 + brr, kc * 2 + bc16));
#pragma unroll
                for (int nf = 0; nf < 8; nf++)
                    mma16816(s[nf], qf[kc], &kb[nf >> 1][(nf & 1) * 2]);
            }

            int qr0 = qlo + gid, qr1 = qr0 + 8;
            float tm0 = -1e30f, tm1 = -1e30f;
#pragma unroll
            for (int nf = 0; nf < 8; nf++) {
                int j0 = k0 + nf * 8 + tig * 2;
#pragma unroll
                for (int e = 0; e < 4; e++) {
                    int qi = (e & 2) ? qr1 : qr0;
                    int rel = qi - (j0 + (e & 1));
                    bool valid = (rel >= 0) && (rel < MAXL);
                    float v = valid ? s[nf][e] * 0.125f + srelp[valid ? rel : 0] : -1e30f;
                    s[nf][e] = v;
                    if (e & 2) tm1 = fmaxf(tm1, v); else tm0 = fmaxf(tm0, v);
                }
            }
            tm0 = fmaxf(tm0, __shfl_xor_sync(0xffffffffu, tm0, 1));
            tm0 = fmaxf(tm0, __shfl_xor_sync(0xffffffffu, tm0, 2));
            tm1 = fmaxf(tm1, __shfl_xor_sync(0xffffffffu, tm1, 1));
            tm1 = fmaxf(tm1, __shfl_xor_sync(0xffffffffu, tm1, 2));
            float n0 = fmaxf(m0, tm0), n1 = fmaxf(m1, tm1);
            float a0 = __expf(m0 - n0), a1 = __expf(m1 - n1);
            m0 = n0; m1 = n1;
            float ts0 = 0.f, ts1 = 0.f;
#pragma unroll
            for (int nf = 0; nf < 8; nf++) {
                s[nf][0] = __expf(s[nf][0] - n0);
                s[nf][1] = __expf(s[nf][1] - n0);
                s[nf][2] = __expf(s[nf][2] - n1);
                s[nf][3] = __expf(s[nf][3] - n1);
                ts0 += s[nf][0] + s[nf][1];
                ts1 += s[nf][2] + s[nf][3];
            }
            ts0 += __shfl_xor_sync(0xffffffffu, ts0, 1);
            ts0 += __shfl_xor_sync(0xffffffffu, ts0, 2);
            ts1 += __shfl_xor_sync(0xffffffffu, ts1, 1);
            ts1 += __shfl_xor_sync(0xffffffffu, ts1, 2);
            l0 = l0 * a0 + ts0;
            l1 = l1 * a1 + ts1;
#pragma unroll
            for (int nf = 0; nf < 8; nf++) {
                o[nf][0] *= a0; o[nf][1] *= a0;
                o[nf][2] *= a1; o[nf][3] *= a1;
            }

            uint32_t pf[4][4];
#pragma unroll
            for (int kc = 0; kc < 4; kc++) {
                pf[kc][0] = packh2(s[2 * kc][0], s[2 * kc][1]);
                pf[kc][1] = packh2(s[2 * kc][2], s[2 * kc][3]);
                pf[kc][2] = packh2(s[2 * kc + 1][0], s[2 * kc + 1][1]);
                pf[kc][3] = packh2(s[2 * kc + 1][2], s[2 * kc + 1][3]);
            }
#pragma unroll
            for (int kc = 0; kc < 4; kc++) {
                uint32_t vb[4][4];
#pragma unroll
                for (int vt = 0; vt < 4; vt++)
                    ldm4t(vb[vt], vbase + swz(kc * 16 + vrr, vt * 2 + vc16));
#pragma unroll
                for (int nf = 0; nf < 8; nf++)
                    mma16816(o[nf], pf[kc], &vb[nf >> 1][(nf & 1) * 2]);
            }
        }
        __syncthreads();
    }

    float i0 = 1.0f / l0, i1 = 1.0f / l1;
    int r0 = qlo + gid;
#pragma unroll
    for (int nf = 0; nf < 8; nf++) {
        int col = h * DDIM + nf * 8 + tig * 2;
        *(__half2*)(outp + (size_t)(b * SEQ + r0) * EDIM + col) =
            __floats2half2_rn(o[nf][0] * i0, o[nf][1] * i0);
        *(__half2*)(outp + (size_t)(b * SEQ + r0 + 8) * EDIM + col) =
            __floats2half2_rn(o[nf][2] * i1, o[nf][3] * i1);
    }
}

// ======================= launch =======================
extern "C" void kernel_launch(void* const* d_in, const int* in_sizes, int n_in,
                              void* d_out, int out_size) {
    (void)in_sizes; (void)n_in; (void)out_size;
    const float* x    = (const float*)d_in[0];
    const float* relp = (const float*)d_in[1];
    const float* ipw  = (const float*)d_in[2];
    const float* ipb  = (const float*)d_in[3];
    const float* ow   = (const float*)d_in[4];
    const float* ob   = (const float*)d_in[5];
    const float* w1   = (const float*)d_in[6];
    const float* b1   = (const float*)d_in[7];
    const float* w2   = (const float*)d_in[8];
    const float* b2   = (const float*)d_in[9];
    const float* g1   = (const float*)d_in[10];
    const float* be1  = (const float*)d_in[11];
    const float* g2   = (const float*)d_in[12];
    const float* be2  = (const float*)d_in[13];
    float* out = (float*)d_out;

    float* p_x1;
    __half *p_xn, *p_qkv, *p_att, *p_xm, *p_h;
    __half *p_ipw, *p_ow, *p_w1, *p_w2;
    cudaGetSymbolAddress((void**)&p_x1,  g_x1);
    cudaGetSymbolAddress((void**)&p_xn,  g_xn);
    cudaGetSymbolAddress((void**)&p_qkv, g_qkvh);
    cudaGetSymbolAddress((void**)&p_att, g_att);
    cudaGetSymbolAddress((void**)&p_xm,  g_xm);
    cudaGetSymbolAddress((void**)&p_h,   g_hb);
    cudaGetSymbolAddress((void**)&p_ipw, g_ipw16);
    cudaGetSymbolAddress((void**)&p_ow,  g_ow16);
    cudaGetSymbolAddress((void**)&p_w1,  g_w116);
    cudaGetSymbolAddress((void**)&p_w2,  g_w216);

    cudaFuncSetAttribute(gemm_mma<false, false, false>,
                         cudaFuncAttributeMaxDynamicSharedMemorySize, GSMEM);
    cudaFuncSetAttribute(gemm_mma<false, true, true>,
                         cudaFuncAttributeMaxDynamicSharedMemorySize, GSMEM);
    cudaFuncSetAttribute(gemm_mma<true, false, false>,
                         cudaFuncAttributeMaxDynamicSharedMemorySize, GSMEM);
    cudaFuncSetAttribute(attn_kernel,
                         cudaFuncAttributeMaxDynamicSharedMemorySize, AT_SMEM);

    // 0. fused weight convert (fp16)
    convert_all_kernel<<<(N4_TOT + 255) / 256, 256>>>(
        (const float4*)ipw, (const float4*)ow, (const float4*)w1, (const float4*)w2,
        (__half2*)p_ipw, (__half2*)p_ow, (__half2*)p_w1, (__half2*)p_w2);

    // 1. ln1 -> xn fp16
    ln_kernel<<<ROWS, 256>>>(x, g1, be1, p_xn);
    // 2. qkv (fp16 out)  grid (Nc/128, M/256)
    gemm_mma<false, false, false><<<dim3(24, 16), 512, GSMEM>>>(
        p_xn, p_ipw, ipb, nullptr, nullptr, p_qkv, 3 * EDIM, EDIM);
    // 3. flash attention (fp16 out)
    attn_kernel<<<dim3(SEQ / 128, BATCH * HNUM), 256, AT_SMEM>>>(p_qkv, relp, p_att);
    // 4. x1 = x + att @ ow^T + ob (fp32 out)
    gemm_mma<false, true, true><<<dim3(8, 16), 512, GSMEM>>>(
        p_att, p_ow, ob, x, p_x1, nullptr, EDIM, EDIM);
    // 5. ln2 -> xm fp16
    ln_kernel<<<ROWS, 256>>>(p_x1, g2, be2, p_xm);
    // 6. h = relu(xm @ w1^T + b1) fp16 out
    gemm_mma<true, false, false><<<dim3(32, 16), 512, GSMEM>>>(
        p_xm, p_w1, b1, nullptr, nullptr, p_h, 4 * EDIM, EDIM);
    // 7. out = x1 + h @ w2^T + b2 (fp32 out)
    gemm_mma<false, true, true><<<dim3(8, 16), 512, GSMEM>>>(
        p_h, p_w2, b2, p_x1, out, nullptr, EDIM, 4 * EDIM);
}